// round 1
// baseline (speedup 1.0000x reference)
#include <cuda_runtime.h>
#include <cuda_bf16.h>
#include <mma.h>
#include <cstdint>

using namespace nvcuda;

// Problem shape (fixed for this bench): x [4,2048,4096] -> M=8192 rows, K=4096; W [4096,4096] (out,in)
#define M_DIM 8192
#define N_DIM 4096
#define K_DIM 4096

// ---------------- device scratch (static allocation: allowed) ----------------
__device__ unsigned int g_mm[4];                         // {xmin,xmax,wmin,wmax} order-encoded
__device__ float  g_qp[6];                               // sx, zx, sw, zw, s=sx*sw, (spare)
__device__ double g_kzz;                                 // K * zx * zw (exact in double)
__device__ __nv_bfloat16 g_qx[(size_t)M_DIM * K_DIM];    // 64 MB
__device__ __nv_bfloat16 g_qw[(size_t)N_DIM * K_DIM];    // 32 MB
__device__ int g_rsx[M_DIM];
__device__ int g_rsw[N_DIM];

// ---------------- order-preserving float<->uint encode for atomic min/max ----
__device__ __forceinline__ unsigned f2ord(float f) {
    unsigned u = __float_as_uint(f);
    return (u & 0x80000000u) ? ~u : (u | 0x80000000u);
}
__device__ __forceinline__ float ord2f(unsigned u) {
    unsigned b = (u & 0x80000000u) ? (u ^ 0x80000000u) : ~u;
    return __uint_as_float(b);
}

__global__ void init_kernel() {
    if (threadIdx.x < 1) {
        g_mm[0] = 0xFFFFFFFFu;  // min slot (atomicMin)
        g_mm[1] = 0u;           // max slot (atomicMax)
        g_mm[2] = 0xFFFFFFFFu;
        g_mm[3] = 0u;
    }
}

// ---------------- global min/max reduction ----------------
__global__ void minmax_kernel(const float* __restrict__ p, int n, int slot) {
    int n4 = n >> 2;
    float mn =  3.4e38f, mx = -3.4e38f;
    int idx = blockIdx.x * blockDim.x + threadIdx.x;
    int stride = gridDim.x * blockDim.x;
    const float4* p4 = (const float4*)p;
    for (int i = idx; i < n4; i += stride) {
        float4 v = p4[i];
        mn = fminf(mn, fminf(fminf(v.x, v.y), fminf(v.z, v.w)));
        mx = fmaxf(mx, fmaxf(fmaxf(v.x, v.y), fmaxf(v.z, v.w)));
    }
    if (blockIdx.x == 0 && threadIdx.x < (n & 3)) {      // tail (unused here, n%4==0)
        float v = p[(n4 << 2) + threadIdx.x];
        mn = fminf(mn, v); mx = fmaxf(mx, v);
    }
    // warp reduce
    #pragma unroll
    for (int o = 16; o; o >>= 1) {
        mn = fminf(mn, __shfl_xor_sync(0xFFFFFFFFu, mn, o));
        mx = fmaxf(mx, __shfl_xor_sync(0xFFFFFFFFu, mx, o));
    }
    __shared__ float smn[8], smx[8];
    int lane = threadIdx.x & 31, wid = threadIdx.x >> 5;
    if (lane == 0) { smn[wid] = mn; smx[wid] = mx; }
    __syncthreads();
    if (wid == 0) {
        mn = (lane < (blockDim.x >> 5)) ? smn[lane] :  3.4e38f;
        mx = (lane < (blockDim.x >> 5)) ? smx[lane] : -3.4e38f;
        #pragma unroll
        for (int o = 4; o; o >>= 1) {
            mn = fminf(mn, __shfl_xor_sync(0xFFFFFFFFu, mn, o));
            mx = fmaxf(mx, __shfl_xor_sync(0xFFFFFFFFu, mx, o));
        }
        if (lane == 0) {
            atomicMin(&g_mm[slot],     f2ord(mn));
            atomicMax(&g_mm[slot + 1], f2ord(mx));
        }
    }
}

// ---------------- compute scale / zero_point exactly like jax fp32 ----------------
__global__ void scales_kernel() {
    if (threadIdx.x == 0) {
        float xmn = ord2f(g_mm[0]), xmx = ord2f(g_mm[1]);
        float wmn = ord2f(g_mm[2]), wmx = ord2f(g_mm[3]);
        float sx = (xmx - xmn) / 255.0f;
        float zx = rintf(-128.0f - xmn / sx);        // round-half-even, matches jnp.round
        float sw = (wmx - wmn) / 255.0f;
        float zw = rintf(-128.0f - wmn / sw);
        g_qp[0] = sx; g_qp[1] = zx; g_qp[2] = sw; g_qp[3] = zw;
        g_qp[4] = sx * sw;
        g_kzz = (double)zx * (double)zw * (double)K_DIM;
    }
}

// ---------------- quantize + per-row integer sum (one block per row) ----------------
// which = 0 -> x into g_qx/g_rsx with (sx,zx); which = 1 -> W into g_qw/g_rsw with (sw,zw)
__global__ void quant_kernel(const float* __restrict__ src, int which) {
    const float s = g_qp[which ? 2 : 0];
    const float z = g_qp[which ? 3 : 1];
    __nv_bfloat16* dst = which ? g_qw : g_qx;
    int* rs = which ? g_rsw : g_rsx;

    int row = blockIdx.x;
    const float4* src4 = (const float4*)(src + (size_t)row * K_DIM);
    __nv_bfloat162* d2 = (__nv_bfloat162*)(dst + (size_t)row * K_DIM);
    int acc = 0;
    for (int j = threadIdx.x; j < (K_DIM >> 2); j += blockDim.x) {
        float4 v = src4[j];
        float q0 = fminf(fmaxf(rintf(v.x / s) + z, -128.0f), 127.0f);
        float q1 = fminf(fmaxf(rintf(v.y / s) + z, -128.0f), 127.0f);
        float q2 = fminf(fmaxf(rintf(v.z / s) + z, -128.0f), 127.0f);
        float q3 = fminf(fmaxf(rintf(v.w / s) + z, -128.0f), 127.0f);
        acc += (int)q0 + (int)q1 + (int)q2 + (int)q3;
        __nv_bfloat162 ab, cd;
        ab.x = __float2bfloat16(q0); ab.y = __float2bfloat16(q1);
        cd.x = __float2bfloat16(q2); cd.y = __float2bfloat16(q3);
        d2[j * 2]     = ab;
        d2[j * 2 + 1] = cd;
    }
    // block reduce int
    #pragma unroll
    for (int o = 16; o; o >>= 1) acc += __shfl_xor_sync(0xFFFFFFFFu, acc, o);
    __shared__ int sacc[8];
    int lane = threadIdx.x & 31, wid = threadIdx.x >> 5;
    if (lane == 0) sacc[wid] = acc;
    __syncthreads();
    if (wid == 0) {
        acc = (lane < (blockDim.x >> 5)) ? sacc[lane] : 0;
        #pragma unroll
        for (int o = 4; o; o >>= 1) acc += __shfl_xor_sync(0xFFFFFFFFu, acc, o);
        if (lane == 0) rs[row] = acc;
    }
}

// ---------------- bf16 wmma GEMM: C = qx @ qw^T, corrected epilogue ----------------
#define BM 128
#define BN 128
#define BK 32
#define LDT 48   // smem tile leading dim (elements); 48*2=96 B, multiple of 16

__global__ __launch_bounds__(256) void gemm_kernel(const float* __restrict__ bias,
                                                   float* __restrict__ out) {
    __shared__ __align__(16) __nv_bfloat16 As[BM * LDT];   // 12288 B
    __shared__ __align__(16) __nv_bfloat16 Bs[BN * LDT];   // 12288 B

    const int m0 = blockIdx.y * BM;
    const int n0 = blockIdx.x * BN;
    const int tid = threadIdx.x;
    const int wid = tid >> 5, lane = tid & 31;
    const int warp_m = wid & 1;        // 2 warps over M -> 64 rows each
    const int warp_n = wid >> 1;       // 4 warps over N -> 32 cols each

    wmma::fragment<wmma::accumulator, 16, 16, 16, float> c[4][2];
    #pragma unroll
    for (int i = 0; i < 4; i++)
        #pragma unroll
        for (int j = 0; j < 2; j++) wmma::fill_fragment(c[i][j], 0.0f);

    const __nv_bfloat16* Ag = g_qx + (size_t)m0 * K_DIM;
    const __nv_bfloat16* Bg = g_qw + (size_t)n0 * K_DIM;

    const int lr = tid >> 2;            // 0..63
    const int lk = (tid & 3) * 8;       // 0,8,16,24

    for (int kt = 0; kt < K_DIM; kt += BK) {
        *(uint4*)&As[lr * LDT + lk]        = *(const uint4*)&Ag[(size_t)lr * K_DIM + kt + lk];
        *(uint4*)&As[(lr + 64) * LDT + lk] = *(const uint4*)&Ag[(size_t)(lr + 64) * K_DIM + kt + lk];
        *(uint4*)&Bs[lr * LDT + lk]        = *(const uint4*)&Bg[(size_t)lr * K_DIM + kt + lk];
        *(uint4*)&Bs[(lr + 64) * LDT + lk] = *(const uint4*)&Bg[(size_t)(lr + 64) * K_DIM + kt + lk];
        __syncthreads();

        #pragma unroll
        for (int ks = 0; ks < BK; ks += 16) {
            wmma::fragment<wmma::matrix_a, 16, 16, 16, __nv_bfloat16, wmma::row_major> a[4];
            wmma::fragment<wmma::matrix_b, 16, 16, 16, __nv_bfloat16, wmma::col_major> b[2];
            #pragma unroll
            for (int i = 0; i < 4; i++)
                wmma::load_matrix_sync(a[i], &As[(warp_m * 64 + i * 16) * LDT + ks], LDT);
            #pragma unroll
            for (int j = 0; j < 2; j++)
                wmma::load_matrix_sync(b[j], &Bs[(warp_n * 32 + j * 16) * LDT + ks], LDT);
            #pragma unroll
            for (int i = 0; i < 4; i++)
                #pragma unroll
                for (int j = 0; j < 2; j++)
                    wmma::mma_sync(c[i][j], a[i], b[j], c[i][j]);
        }
        __syncthreads();
    }

    // epilogue: out = s*(acc - zw*rsx[m] - zx*rsw[n] + K*zx*zw) + bias[n]
    const float  s   = g_qp[4];
    const double zxd = (double)g_qp[1];
    const double zwd = (double)g_qp[3];
    const double kzz = g_kzz;

    float* scr = reinterpret_cast<float*>(As) + wid * 16 * 24;   // 1536 B/warp, fits in As
    const int er = lane >> 1;           // row within 16x16 frag
    const int ec0 = (lane & 1) * 8;     // col start

    #pragma unroll
    for (int i = 0; i < 4; i++) {
        #pragma unroll
        for (int j = 0; j < 2; j++) {
            wmma::store_matrix_sync(scr, c[i][j], 24, wmma::mem_row_major);
            __syncwarp();
            const int gm  = m0 + warp_m * 64 + i * 16 + er;
            const int gn0 = n0 + warp_n * 32 + j * 16 + ec0;
            const double rxm = zwd * (double)g_rsx[gm];
            float* op = out + (size_t)gm * N_DIM + gn0;
            #pragma unroll
            for (int t = 0; t < 8; t++) {
                const int gn = gn0 + t;
                double corr = (double)scr[er * 24 + ec0 + t] - rxm
                            - zxd * (double)g_rsw[gn] + kzz;
                op[t] = s * (float)corr + bias[gn];
            }
            __syncwarp();
        }
    }
}

// ---------------- launch ----------------
extern "C" void kernel_launch(void* const* d_in, const int* in_sizes, int n_in,
                              void* d_out, int out_size) {
    const float* x    = (const float*)d_in[0];
    const float* W    = (const float*)d_in[1];
    const float* bias = (const float*)d_in[2];
    float* out = (float*)d_out;

    init_kernel<<<1, 32>>>();
    minmax_kernel<<<2048, 256>>>(x, M_DIM * K_DIM, 0);
    minmax_kernel<<<2048, 256>>>(W, N_DIM * K_DIM, 2);
    scales_kernel<<<1, 32>>>();
    quant_kernel<<<M_DIM, 256>>>(x, 0);
    quant_kernel<<<N_DIM, 256>>>(W, 1);
    dim3 grid(N_DIM / BN, M_DIM / BM);   // 32 x 64
    gemm_kernel<<<grid, 256>>>(bias, out);
}

// round 2
// speedup vs baseline: 1.0014x; 1.0014x over previous
#include <cuda_runtime.h>
#include <cuda_bf16.h>
#include <mma.h>
#include <cstdint>

using namespace nvcuda;

// Problem shape (fixed for this bench): x [4,2048,4096] -> M=8192 rows, K=4096; W [4096,4096] (out,in)
#define M_DIM 8192
#define N_DIM 4096
#define K_DIM 4096

// ---------------- device scratch (static allocation: allowed) ----------------
__device__ unsigned int g_mm[4];                         // {xmin,xmax,wmin,wmax} order-encoded
__device__ float  g_qp[6];                               // sx, zx, sw, zw, s=sx*sw, (spare)
__device__ double g_kzz;                                 // K * zx * zw (exact in double)
__device__ __nv_bfloat16 g_qx[(size_t)M_DIM * K_DIM];    // 64 MB
__device__ __nv_bfloat16 g_qw[(size_t)N_DIM * K_DIM];    // 32 MB
__device__ int g_rsx[M_DIM];
__device__ int g_rsw[N_DIM];

// ---------------- order-preserving float<->uint encode for atomic min/max ----
__device__ __forceinline__ unsigned f2ord(float f) {
    unsigned u = __float_as_uint(f);
    return (u & 0x80000000u) ? ~u : (u | 0x80000000u);
}
__device__ __forceinline__ float ord2f(unsigned u) {
    unsigned b = (u & 0x80000000u) ? (u ^ 0x80000000u) : ~u;
    return __uint_as_float(b);
}

__global__ void init_kernel() {
    if (threadIdx.x < 1) {
        g_mm[0] = 0xFFFFFFFFu;  // min slot (atomicMin)
        g_mm[1] = 0u;           // max slot (atomicMax)
        g_mm[2] = 0xFFFFFFFFu;
        g_mm[3] = 0u;
    }
}

// ---------------- global min/max reduction ----------------
__global__ void minmax_kernel(const float* __restrict__ p, int n, int slot) {
    int n4 = n >> 2;
    float mn =  3.4e38f, mx = -3.4e38f;
    int idx = blockIdx.x * blockDim.x + threadIdx.x;
    int stride = gridDim.x * blockDim.x;
    const float4* p4 = (const float4*)p;
    for (int i = idx; i < n4; i += stride) {
        float4 v = p4[i];
        mn = fminf(mn, fminf(fminf(v.x, v.y), fminf(v.z, v.w)));
        mx = fmaxf(mx, fmaxf(fmaxf(v.x, v.y), fmaxf(v.z, v.w)));
    }
    if (blockIdx.x == 0 && threadIdx.x < (n & 3)) {      // tail (unused here, n%4==0)
        float v = p[(n4 << 2) + threadIdx.x];
        mn = fminf(mn, v); mx = fmaxf(mx, v);
    }
    // warp reduce
    #pragma unroll
    for (int o = 16; o; o >>= 1) {
        mn = fminf(mn, __shfl_xor_sync(0xFFFFFFFFu, mn, o));
        mx = fmaxf(mx, __shfl_xor_sync(0xFFFFFFFFu, mx, o));
    }
    __shared__ float smn[8], smx[8];
    int lane = threadIdx.x & 31, wid = threadIdx.x >> 5;
    if (lane == 0) { smn[wid] = mn; smx[wid] = mx; }
    __syncthreads();
    if (wid == 0) {
        mn = (lane < (blockDim.x >> 5)) ? smn[lane] :  3.4e38f;
        mx = (lane < (blockDim.x >> 5)) ? smx[lane] : -3.4e38f;
        #pragma unroll
        for (int o = 4; o; o >>= 1) {
            mn = fminf(mn, __shfl_xor_sync(0xFFFFFFFFu, mn, o));
            mx = fmaxf(mx, __shfl_xor_sync(0xFFFFFFFFu, mx, o));
        }
        if (lane == 0) {
            atomicMin(&g_mm[slot],     f2ord(mn));
            atomicMax(&g_mm[slot + 1], f2ord(mx));
        }
    }
}

// ---------------- compute scale / zero_point exactly like jax fp32 ----------------
__global__ void scales_kernel() {
    if (threadIdx.x == 0) {
        float xmn = ord2f(g_mm[0]), xmx = ord2f(g_mm[1]);
        float wmn = ord2f(g_mm[2]), wmx = ord2f(g_mm[3]);
        float sx = (xmx - xmn) / 255.0f;
        float zx = rintf(-128.0f - xmn / sx);        // round-half-even, matches jnp.round
        float sw = (wmx - wmn) / 255.0f;
        float zw = rintf(-128.0f - wmn / sw);
        g_qp[0] = sx; g_qp[1] = zx; g_qp[2] = sw; g_qp[3] = zw;
        g_qp[4] = sx * sw;
        g_kzz = (double)zx * (double)zw * (double)K_DIM;
    }
}

// ---------------- quantize + per-row integer sum (one block per row) ----------------
// which = 0 -> x into g_qx/g_rsx with (sx,zx); which = 1 -> W into g_qw/g_rsw with (sw,zw)
__global__ void quant_kernel(const float* __restrict__ src, int which) {
    const float s = g_qp[which ? 2 : 0];
    const float z = g_qp[which ? 3 : 1];
    __nv_bfloat16* dst = which ? g_qw : g_qx;
    int* rs = which ? g_rsw : g_rsx;

    int row = blockIdx.x;
    const float4* src4 = (const float4*)(src + (size_t)row * K_DIM);
    __nv_bfloat162* d2 = (__nv_bfloat162*)(dst + (size_t)row * K_DIM);
    int acc = 0;
    for (int j = threadIdx.x; j < (K_DIM >> 2); j += blockDim.x) {
        float4 v = src4[j];
        float q0 = fminf(fmaxf(rintf(v.x / s) + z, -128.0f), 127.0f);
        float q1 = fminf(fmaxf(rintf(v.y / s) + z, -128.0f), 127.0f);
        float q2 = fminf(fmaxf(rintf(v.z / s) + z, -128.0f), 127.0f);
        float q3 = fminf(fmaxf(rintf(v.w / s) + z, -128.0f), 127.0f);
        acc += (int)q0 + (int)q1 + (int)q2 + (int)q3;
        __nv_bfloat162 ab, cd;
        ab.x = __float2bfloat16(q0); ab.y = __float2bfloat16(q1);
        cd.x = __float2bfloat16(q2); cd.y = __float2bfloat16(q3);
        d2[j * 2]     = ab;
        d2[j * 2 + 1] = cd;
    }
    // block reduce int
    #pragma unroll
    for (int o = 16; o; o >>= 1) acc += __shfl_xor_sync(0xFFFFFFFFu, acc, o);
    __shared__ int sacc[8];
    int lane = threadIdx.x & 31, wid = threadIdx.x >> 5;
    if (lane == 0) sacc[wid] = acc;
    __syncthreads();
    if (wid == 0) {
        acc = (lane < (blockDim.x >> 5)) ? sacc[lane] : 0;
        #pragma unroll
        for (int o = 4; o; o >>= 1) acc += __shfl_xor_sync(0xFFFFFFFFu, acc, o);
        if (lane == 0) rs[row] = acc;
    }
}

// ---------------- bf16 wmma GEMM: C = qx @ qw^T, corrected epilogue ----------------
#define BM 128
#define BN 128
#define BK 32
#define LDT 48   // smem tile leading dim (elements); 48*2=96 B, multiple of 16

__global__ __launch_bounds__(256) void gemm_kernel(const float* __restrict__ bias,
                                                   float* __restrict__ out) {
    __shared__ __align__(16) __nv_bfloat16 As[BM * LDT];   // 12288 B
    __shared__ __align__(16) __nv_bfloat16 Bs[BN * LDT];   // 12288 B

    const int m0 = blockIdx.y * BM;
    const int n0 = blockIdx.x * BN;
    const int tid = threadIdx.x;
    const int wid = tid >> 5, lane = tid & 31;
    const int warp_m = wid & 1;        // 2 warps over M -> 64 rows each
    const int warp_n = wid >> 1;       // 4 warps over N -> 32 cols each

    wmma::fragment<wmma::accumulator, 16, 16, 16, float> c[4][2];
    #pragma unroll
    for (int i = 0; i < 4; i++)
        #pragma unroll
        for (int j = 0; j < 2; j++) wmma::fill_fragment(c[i][j], 0.0f);

    const __nv_bfloat16* Ag = g_qx + (size_t)m0 * K_DIM;
    const __nv_bfloat16* Bg = g_qw + (size_t)n0 * K_DIM;

    const int lr = tid >> 2;            // 0..63
    const int lk = (tid & 3) * 8;       // 0,8,16,24

    for (int kt = 0; kt < K_DIM; kt += BK) {
        *(uint4*)&As[lr * LDT + lk]        = *(const uint4*)&Ag[(size_t)lr * K_DIM + kt + lk];
        *(uint4*)&As[(lr + 64) * LDT + lk] = *(const uint4*)&Ag[(size_t)(lr + 64) * K_DIM + kt + lk];
        *(uint4*)&Bs[lr * LDT + lk]        = *(const uint4*)&Bg[(size_t)lr * K_DIM + kt + lk];
        *(uint4*)&Bs[(lr + 64) * LDT + lk] = *(const uint4*)&Bg[(size_t)(lr + 64) * K_DIM + kt + lk];
        __syncthreads();

        #pragma unroll
        for (int ks = 0; ks < BK; ks += 16) {
            wmma::fragment<wmma::matrix_a, 16, 16, 16, __nv_bfloat16, wmma::row_major> a[4];
            wmma::fragment<wmma::matrix_b, 16, 16, 16, __nv_bfloat16, wmma::col_major> b[2];
            #pragma unroll
            for (int i = 0; i < 4; i++)
                wmma::load_matrix_sync(a[i], &As[(warp_m * 64 + i * 16) * LDT + ks], LDT);
            #pragma unroll
            for (int j = 0; j < 2; j++)
                wmma::load_matrix_sync(b[j], &Bs[(warp_n * 32 + j * 16) * LDT + ks], LDT);
            #pragma unroll
            for (int i = 0; i < 4; i++)
                #pragma unroll
                for (int j = 0; j < 2; j++)
                    wmma::mma_sync(c[i][j], a[i], b[j], c[i][j]);
        }
        __syncthreads();
    }

    // epilogue: out = s*(acc - zw*rsx[m] - zx*rsw[n] + K*zx*zw) + bias[n]
    const float  s   = g_qp[4];
    const double zxd = (double)g_qp[1];
    const double zwd = (double)g_qp[3];
    const double kzz = g_kzz;

    float* scr = reinterpret_cast<float*>(As) + wid * 16 * 24;   // 1536 B/warp, fits in As
    const int er = lane >> 1;           // row within 16x16 frag
    const int ec0 = (lane & 1) * 8;     // col start

    #pragma unroll
    for (int i = 0; i < 4; i++) {
        #pragma unroll
        for (int j = 0; j < 2; j++) {
            wmma::store_matrix_sync(scr, c[i][j], 24, wmma::mem_row_major);
            __syncwarp();
            const int gm  = m0 + warp_m * 64 + i * 16 + er;
            const int gn0 = n0 + warp_n * 32 + j * 16 + ec0;
            const double rxm = zwd * (double)g_rsx[gm];
            float* op = out + (size_t)gm * N_DIM + gn0;
            #pragma unroll
            for (int t = 0; t < 8; t++) {
                const int gn = gn0 + t;
                double corr = (double)scr[er * 24 + ec0 + t] - rxm
                            - zxd * (double)g_rsw[gn] + kzz;
                op[t] = s * (float)corr + bias[gn];
            }
            __syncwarp();
        }
    }
}

// ---------------- launch ----------------
extern "C" void kernel_launch(void* const* d_in, const int* in_sizes, int n_in,
                              void* d_out, int out_size) {
    const float* x    = (const float*)d_in[0];
    const float* W    = (const float*)d_in[1];
    const float* bias = (const float*)d_in[2];
    float* out = (float*)d_out;

    init_kernel<<<1, 32>>>();
    minmax_kernel<<<2048, 256>>>(x, M_DIM * K_DIM, 0);
    minmax_kernel<<<2048, 256>>>(W, N_DIM * K_DIM, 2);
    scales_kernel<<<1, 32>>>();
    quant_kernel<<<M_DIM, 256>>>(x, 0);
    quant_kernel<<<N_DIM, 256>>>(W, 1);
    dim3 grid(N_DIM / BN, M_DIM / BM);   // 32 x 64
    gemm_kernel<<<grid, 256>>>(bias, out);
}